// round 2
// baseline (speedup 1.0000x reference)
#include <cuda_runtime.h>
#include <math.h>

#define BDIM 8192
#define HDIM 2048
#define TOPK 32
#define NEGINF (-INFINITY)

// Scratch (static device globals — no allocation allowed)
__device__ float g_sim[(size_t)BDIM * BDIM];   // 256 MB similarity matrix
__device__ float g_invn[BDIM];
__device__ int   g_topidx[BDIM * TOPK];
__device__ float g_topw[BDIM * TOPK];

// ---------------- K0: row inverse norms ----------------
__global__ __launch_bounds__(256) void norms_kernel(const float* __restrict__ hs) {
    int row = blockIdx.x;
    const float* p = hs + (size_t)row * HDIM;
    float s = 0.f;
    for (int c = threadIdx.x; c < HDIM; c += 256) { float v = p[c]; s += v * v; }
    __shared__ float red[8];
    for (int o = 16; o; o >>= 1) s += __shfl_down_sync(0xffffffffu, s, o);
    if ((threadIdx.x & 31) == 0) red[threadIdx.x >> 5] = s;
    __syncthreads();
    if (threadIdx.x < 32) {
        float v = (threadIdx.x < 8) ? red[threadIdx.x] : 0.f;
        for (int o = 4; o; o >>= 1) v += __shfl_down_sync(0xffffffffu, v, o);
        if (threadIdx.x == 0) {
            float n = fmaxf(sqrtf(v), 1e-12f);
            g_invn[row] = 1.0f / n;
        }
    }
}

// ---------------- K1: sim = H * H^T, scaled + masked ----------------
#define BM 128
#define BN 128
#define BK 16
#define TM 8
#define TN 8

__global__ __launch_bounds__(256) void simgemm_kernel(const float* __restrict__ hs,
                                                      const int* __restrict__ mask) {
    __shared__ float As[BK][BM + 4];
    __shared__ float Bs[BK][BN + 4];
    const int bi = blockIdx.y, bj = blockIdx.x;
    const int tid = threadIdx.x;
    const int tx = tid & 15, ty = tid >> 4;
    const float* Arow = hs + (size_t)(bi * BM) * HDIM;
    const float* Brow = hs + (size_t)(bj * BN) * HDIM;

    float acc[TM][TN];
    #pragma unroll
    for (int i = 0; i < TM; i++)
        #pragma unroll
        for (int j = 0; j < TN; j++) acc[i][j] = 0.f;

    for (int k0 = 0; k0 < HDIM; k0 += BK) {
        #pragma unroll
        for (int t = 0; t < 2; t++) {
            int l = tid + t * 256;       // 0..511 -> 128 rows x 4 float4
            int r = l >> 2;
            int c4 = (l & 3) * 4;
            float4 v = *(const float4*)(Arow + (size_t)r * HDIM + k0 + c4);
            As[c4 + 0][r] = v.x; As[c4 + 1][r] = v.y; As[c4 + 2][r] = v.z; As[c4 + 3][r] = v.w;
            float4 w = *(const float4*)(Brow + (size_t)r * HDIM + k0 + c4);
            Bs[c4 + 0][r] = w.x; Bs[c4 + 1][r] = w.y; Bs[c4 + 2][r] = w.z; Bs[c4 + 3][r] = w.w;
        }
        __syncthreads();
        #pragma unroll
        for (int k = 0; k < BK; k++) {
            float ra[TM], rb[TN];
            #pragma unroll
            for (int i = 0; i < TM; i++) ra[i] = As[k][ty * TM + i];
            #pragma unroll
            for (int j = 0; j < TN; j++) rb[j] = Bs[k][tx * TN + j];
            #pragma unroll
            for (int i = 0; i < TM; i++)
                #pragma unroll
                for (int j = 0; j < TN; j++)
                    acc[i][j] = fmaf(ra[i], rb[j], acc[i][j]);
        }
        __syncthreads();
    }

    #pragma unroll
    for (int i = 0; i < TM; i++) {
        int gi = bi * BM + ty * TM + i;
        float sa = g_invn[gi];
        #pragma unroll
        for (int j = 0; j < TN; j++) {
            int gj = bj * BN + tx * TN + j;
            float v = acc[i][j] * sa * g_invn[gj];   // TEMPERATURE = 1
            if (gi == gj || mask[gj] == 0) v = NEGINF;
            g_sim[(size_t)gi * BDIM + gj] = v;
        }
    }
}

// ---------------- K2: per-row top-32 + softmax weights ----------------
__global__ __launch_bounds__(256) void topk_kernel() {
    __shared__ float srow[BDIM];      // 32 KB
    __shared__ float rmax[256];
    __shared__ int   rmaxi[256];
    __shared__ float tvals[TOPK];
    __shared__ int   tidxs[TOPK];
    const int row = blockIdx.x;
    const int tid = threadIdx.x;
    const float* sp = g_sim + (size_t)row * BDIM;
    for (int c = tid; c < BDIM; c += 256) srow[c] = sp[c];
    __syncthreads();

    for (int it = 0; it < TOPK; it++) {
        float m = NEGINF; int mi = -1;
        #pragma unroll 8
        for (int c = tid; c < BDIM; c += 256) {
            float v = srow[c];
            if (v > m) { m = v; mi = c; }
        }
        rmax[tid] = m; rmaxi[tid] = mi;
        __syncthreads();
        for (int s = 128; s > 0; s >>= 1) {
            if (tid < s) {
                if (rmax[tid + s] > rmax[tid]) { rmax[tid] = rmax[tid + s]; rmaxi[tid] = rmaxi[tid + s]; }
            }
            __syncthreads();
        }
        if (tid == 0) {
            tvals[it] = rmax[0];
            tidxs[it] = rmaxi[0];
            if (rmaxi[0] >= 0) srow[rmaxi[0]] = NEGINF;
        }
        __syncthreads();
    }

    if (tid < TOPK) {
        float m = tvals[0];
        float v = tvals[tid];
        float e = (isfinite(v) && isfinite(m)) ? __expf(v - m) : 0.f;
        float s = e;
        for (int o = 16; o; o >>= 1) s += __shfl_down_sync(0xffffffffu, s, o);
        s = __shfl_sync(0xffffffffu, s, 0);
        float w = (s > 0.f) ? e / s : 0.f;
        g_topw[row * TOPK + tid] = w;
        g_topidx[row * TOPK + tid] = (tidxs[tid] >= 0) ? tidxs[tid] : 0;
    }
}

// ---------------- K3: cross = sparse gather, gate, residual ----------------
__global__ __launch_bounds__(256) void cross_gate_kernel(const float* __restrict__ hs,
                                                         const float* __restrict__ gw,
                                                         const float* __restrict__ gb,
                                                         float* __restrict__ out) {
    const int row = blockIdx.x;
    const int tid = threadIdx.x;
    __shared__ float sw[TOPK];
    __shared__ int   si[TOPK];
    __shared__ float red[8];
    __shared__ float gsh;
    if (tid < TOPK) { sw[tid] = g_topw[row * TOPK + tid]; si[tid] = g_topidx[row * TOPK + tid]; }
    __syncthreads();

    float cr[HDIM / 256];
    float p = 0.f;
    #pragma unroll
    for (int u = 0; u < HDIM / 256; u++) {
        int c = tid + u * 256;
        float acc = 0.f;
        #pragma unroll
        for (int k = 0; k < TOPK; k++)
            acc = fmaf(sw[k], hs[(size_t)si[k] * HDIM + c], acc);
        cr[u] = acc;
        float h = hs[(size_t)row * HDIM + c];
        p = fmaf(gw[c], h, p);
        p = fmaf(gw[HDIM + c], acc, p);
    }
    for (int o = 16; o; o >>= 1) p += __shfl_down_sync(0xffffffffu, p, o);
    if ((tid & 31) == 0) red[tid >> 5] = p;
    __syncthreads();
    if (tid < 32) {
        float v = (tid < 8) ? red[tid] : 0.f;
        for (int o = 4; o; o >>= 1) v += __shfl_down_sync(0xffffffffu, v, o);
        if (tid == 0) gsh = 1.f / (1.f + __expf(-(v + gb[0])));
    }
    __syncthreads();
    float g = gsh;
    #pragma unroll
    for (int u = 0; u < HDIM / 256; u++) {
        int c = tid + u * 256;
        float h = hs[(size_t)row * HDIM + c];
        out[(size_t)row * HDIM + c] = h + g * cr[u];
    }
}

extern "C" void kernel_launch(void* const* d_in, const int* in_sizes, int n_in,
                              void* d_out, int out_size) {
    const float* hs  = (const float*)d_in[0];
    const int*   msk = (const int*)d_in[1];
    const float* gw  = (const float*)d_in[2];
    const float* gb  = (const float*)d_in[3];
    float* out       = (float*)d_out;

    norms_kernel<<<BDIM, 256>>>(hs);
    dim3 grid(BDIM / BN, BDIM / BM);
    simgemm_kernel<<<grid, 256>>>(hs, msk);
    topk_kernel<<<BDIM, 256>>>();
    cross_gate_kernel<<<BDIM, 256>>>(hs, gw, gb, out);
}

// round 4
// speedup vs baseline: 3.4236x; 3.4236x over previous
#include <cuda_runtime.h>
#include <cuda_bf16.h>
#include <math.h>
#include <stdint.h>

#define BDIM 8192
#define HDIM 2048
#define TOPK 32
#define CAND 40
#define NEGINF (-INFINITY)

// ---- GEMM tiling ----
#define KCHUNK 64                          // bf16 per K-chunk = 128B rows (swizzle atom)
#define NKC (HDIM / KCHUNK)                // 32
#define TILE_M 128
#define NRB (BDIM / TILE_M)                // 64
#define TILE_ELEMS (TILE_M * KCHUNK)       // 8192 bf16
#define TILE_BYTES (TILE_ELEMS * 2)        // 16384
#define STAGES 3
#define STAGE_BYTES (4 * TILE_BYTES)       // 65536 (Ahi,Alo,Bhi,Blo)
#define SMEM_TOTAL (STAGES * STAGE_BYTES)  // 196608

// ---- device scratch ----
__device__ float g_sim[(size_t)BDIM * BDIM];     // 256 MB
__device__ float g_invn[BDIM];
__device__ int   g_topidx[BDIM * TOPK];
__device__ float g_topw[BDIM * TOPK];
__device__ __nv_bfloat16 g_hi[(size_t)NKC * NRB * TILE_ELEMS];   // 32 MB pre-swizzled tiles
__device__ __nv_bfloat16 g_lo[(size_t)NKC * NRB * TILE_ELEMS];   // 32 MB

// ==================== asm helpers ====================
__device__ __forceinline__ uint32_t smem_u32(const void* p) {
    uint32_t a;
    asm("{ .reg .u64 t; cvta.to.shared.u64 t, %1; cvt.u32.u64 %0, t; }" : "=r"(a) : "l"(p));
    return a;
}

#define CP16(dst, src) \
    asm volatile("cp.async.cg.shared.global [%0], [%1], 16;" :: "r"(dst), "l"(src) : "memory")
#define CPCOMMIT() asm volatile("cp.async.commit_group;" ::: "memory")
#define CPWAIT1()  asm volatile("cp.async.wait_group 1;" ::: "memory")
#define CPWAIT0()  asm volatile("cp.async.wait_group 0;" ::: "memory")

#define LDSM4(r0, r1, r2, r3, addr) \
    asm volatile("ldmatrix.sync.aligned.m8n8.x4.shared.b16 {%0,%1,%2,%3}, [%4];" \
        : "=r"(r0), "=r"(r1), "=r"(r2), "=r"(r3) : "r"(addr))

#define MMA16816(d, a, b) \
    asm volatile("mma.sync.aligned.m16n8k16.row.col.f32.bf16.bf16.f32 " \
        "{%0,%1,%2,%3}, {%4,%5,%6,%7}, {%8,%9}, {%0,%1,%2,%3};" \
        : "+f"((d)[0]), "+f"((d)[1]), "+f"((d)[2]), "+f"((d)[3]) \
        : "r"((a)[0]), "r"((a)[1]), "r"((a)[2]), "r"((a)[3]), "r"((b)[0]), "r"((b)[1]))

// ==================== K0: inverse row norms ====================
__global__ __launch_bounds__(256) void norms_kernel(const float* __restrict__ hs) {
    int row = blockIdx.x;
    const float* p = hs + (size_t)row * HDIM;
    float s = 0.f;
    for (int c = threadIdx.x; c < HDIM; c += 256) { float v = p[c]; s += v * v; }
    __shared__ float red[8];
    for (int o = 16; o; o >>= 1) s += __shfl_down_sync(0xffffffffu, s, o);
    if ((threadIdx.x & 31) == 0) red[threadIdx.x >> 5] = s;
    __syncthreads();
    if (threadIdx.x == 0) {
        float v = 0.f;
        for (int i = 0; i < 8; i++) v += red[i];
        g_invn[row] = 1.0f / fmaxf(sqrtf(v), 1e-12f);
    }
}

// ==================== K1: split into pre-swizzled bf16 hi/lo tiles ====================
// Tile layout: [kc][rowblock] of 128 rows x 64 cols; within a row the 8 16B-chunks
// are stored at chunk' = chunk ^ (row & 7)  (bank-conflict-free for ldmatrix).
__global__ __launch_bounds__(256) void prep_kernel(const float* __restrict__ hs) {
    size_t i4 = (size_t)blockIdx.x * 256 + threadIdx.x;     // one float4 per thread
    int r  = (int)(i4 / (HDIM / 4));
    int k4 = (int)(i4 % (HDIM / 4)) * 4;
    float4 v = *(const float4*)(hs + (size_t)r * HDIM + k4);
    float vv[4] = {v.x, v.y, v.z, v.w};
    int kc = k4 >> 6;
    int rb = r >> 7, rr = r & 127;
    size_t base = ((size_t)(kc * NRB + rb)) * TILE_ELEMS;
    #pragma unroll
    for (int j = 0; j < 4; j++) {
        int c = (k4 + j) & 63;
        uint32_t off = (uint32_t)(rr * 128 + c * 2);
        uint32_t sw  = (off ^ (((uint32_t)(rr & 7)) << 4)) >> 1;   // element index
        float f = vv[j];
        __nv_bfloat16 hi = __float2bfloat16(f);
        __nv_bfloat16 lo = __float2bfloat16(f - __bfloat162float(hi));
        g_hi[base + sw] = hi;
        g_lo[base + sw] = lo;
    }
}

// ==================== K2: sim = H H^T via mma.sync bf16x3, symmetric ====================
__global__ __launch_bounds__(256, 1) void simgemm_mma(const int* __restrict__ mask) {
    const int bj = blockIdx.x, bi = blockIdx.y;
    if (bi > bj) return;
    extern __shared__ __align__(128) char smem[];
    const uint32_t sbase = smem_u32(smem);
    const int tid = threadIdx.x;
    const int lane = tid & 31, wid = tid >> 5;
    const int wm = wid & 1, wn = wid >> 1;          // warp tile: rows wm*64.. cols wn*32..

    float acc[4][4][4];
    #pragma unroll
    for (int a = 0; a < 4; a++)
        #pragma unroll
        for (int b = 0; b < 4; b++)
            #pragma unroll
            for (int c = 0; c < 4; c++) acc[a][b][c] = 0.f;

    const __nv_bfloat16* baseA_hi = g_hi + (size_t)bi * TILE_ELEMS;
    const __nv_bfloat16* baseA_lo = g_lo + (size_t)bi * TILE_ELEMS;
    const __nv_bfloat16* baseB_hi = g_hi + (size_t)bj * TILE_ELEMS;
    const __nv_bfloat16* baseB_lo = g_lo + (size_t)bj * TILE_ELEMS;
    const size_t kc_stride = (size_t)NRB * TILE_ELEMS;

    // ldmatrix per-lane addressing constants
    const int rbase = (lane & 7) + ((lane >> 3) & 1) * 8;   // row within 16-row tile
    const int csel  = lane >> 4;                            // k-chunk select (0/1)

    // ---- async copy of one stage (4 tiles x 16KB), linear copy of swizzled image ----
    auto issue = [&](int kc, int s) {
        uint32_t sb = sbase + s * STAGE_BYTES;
        const char* srcs[4] = {
            (const char*)(baseA_hi + (size_t)kc * kc_stride),
            (const char*)(baseA_lo + (size_t)kc * kc_stride),
            (const char*)(baseB_hi + (size_t)kc * kc_stride),
            (const char*)(baseB_lo + (size_t)kc * kc_stride) };
        #pragma unroll
        for (int t = 0; t < 4; t++) {
            #pragma unroll
            for (int i = 0; i < 4; i++) {
                uint32_t o = (uint32_t)(tid * 16 + i * 4096);
                CP16(sb + t * TILE_BYTES + o, srcs[t] + o);
            }
        }
        CPCOMMIT();
    };

    issue(0, 0);
    issue(1, 1);

    for (int kc = 0; kc < NKC; kc++) {
        CPWAIT1();
        __syncthreads();
        if (kc + 2 < NKC) issue(kc + 2, (kc + 2) % STAGES);

        uint32_t sb = sbase + (kc % STAGES) * STAGE_BYTES;
        #pragma unroll
        for (int k16 = 0; k16 < 4; k16++) {
            uint32_t ahi[4][4], alo[4][4], bhi[4][2], blo[4][2];
            #pragma unroll
            for (int mt = 0; mt < 4; mt++) {
                int row = wm * 64 + mt * 16 + rbase;
                uint32_t off = (uint32_t)(row * 128 + (((k16 * 2 + csel) ^ (row & 7)) * 16));
                LDSM4(ahi[mt][0], ahi[mt][1], ahi[mt][2], ahi[mt][3], sb + off);
                LDSM4(alo[mt][0], alo[mt][1], alo[mt][2], alo[mt][3], sb + TILE_BYTES + off);
            }
            #pragma unroll
            for (int p = 0; p < 2; p++) {
                int row = wn * 32 + p * 16 + rbase;
                uint32_t off = (uint32_t)(row * 128 + (((k16 * 2 + csel) ^ (row & 7)) * 16));
                uint32_t r0, r1, r2, r3;
                LDSM4(r0, r1, r2, r3, sb + 2 * TILE_BYTES + off);
                bhi[2*p][0] = r0; bhi[2*p][1] = r2; bhi[2*p+1][0] = r1; bhi[2*p+1][1] = r3;
                LDSM4(r0, r1, r2, r3, sb + 3 * TILE_BYTES + off);
                blo[2*p][0] = r0; blo[2*p][1] = r2; blo[2*p+1][0] = r1; blo[2*p+1][1] = r3;
            }
            #pragma unroll
            for (int mt = 0; mt < 4; mt++) {
                #pragma unroll
                for (int nt = 0; nt < 4; nt++) {
                    MMA16816(acc[mt][nt], ahi[mt], bhi[nt]);
                    MMA16816(acc[mt][nt], ahi[mt], blo[nt]);
                    MMA16816(acc[mt][nt], alo[mt], bhi[nt]);
                }
            }
        }
    }
    CPWAIT0();

    // ---- epilogue: scale, mask, store (+ mirrored transpose) ----
    const int i0 = bi * 128 + wm * 64;
    const int j0 = bj * 128 + wn * 32;
    const int grp = lane >> 2, qd = lane & 3;
    #pragma unroll
    for (int mt = 0; mt < 4; mt++) {
        #pragma unroll
        for (int half = 0; half < 2; half++) {
            int row = i0 + mt * 16 + grp + half * 8;
            float sa = g_invn[row];
            int mr = mask[row];
            #pragma unroll
            for (int nt = 0; nt < 4; nt++) {
                int col = j0 + nt * 8 + qd * 2;
                float v0 = acc[mt][nt][half * 2 + 0] * sa * g_invn[col];
                float v1 = acc[mt][nt][half * 2 + 1] * sa * g_invn[col + 1];
                float2 o;
                o.x = (row == col     || mask[col]     == 0) ? NEGINF : v0;
                o.y = (row == col + 1 || mask[col + 1] == 0) ? NEGINF : v1;
                *(float2*)(g_sim + (size_t)row * BDIM + col) = o;
                if (bi != bj) {
                    g_sim[(size_t)col * BDIM + row]       = mr ? v0 : NEGINF;
                    g_sim[(size_t)(col + 1) * BDIM + row] = mr ? v1 : NEGINF;
                }
            }
        }
    }
}

// ==================== K3: per-row top-32 (+ exact fp32 fixup) + softmax ====================
__global__ __launch_bounds__(256) void topk_kernel(const float* __restrict__ hs) {
    __shared__ float srow[BDIM];                 // 32 KB
    __shared__ float wv[8];
    __shared__ int   wx[8];
    __shared__ float tvals[CAND];
    __shared__ int   tidxs[CAND];
    __shared__ float exv[CAND];
    const int row = blockIdx.x;
    const int tid = threadIdx.x, wid = tid >> 5, lid = tid & 31;
    const float* sp = g_sim + (size_t)row * BDIM;

    for (int c = tid * 4; c < BDIM; c += 1024)
        *(float4*)(srow + c) = *(const float4*)(sp + c);
    __syncthreads();

    float m = NEGINF; int mi = -1;
    for (int c = tid; c < BDIM; c += 256) { float v = srow[c]; if (v > m) { m = v; mi = c; } }

    for (int it = 0; it < CAND; it++) {
        float v = m; int x = mi;
        #pragma unroll
        for (int o = 16; o; o >>= 1) {
            float ov = __shfl_down_sync(0xffffffffu, v, o);
            int   ox = __shfl_down_sync(0xffffffffu, x, o);
            if (ov > v) { v = ov; x = ox; }
        }
        if (lid == 0) { wv[wid] = v; wx[wid] = x; }
        __syncthreads();
        if (tid == 0) {
            float bv = wv[0]; int bx = wx[0];
            #pragma unroll
            for (int w = 1; w < 8; w++) if (wv[w] > bv) { bv = wv[w]; bx = wx[w]; }
            tvals[it] = bv; tidxs[it] = bx;
        }
        __syncthreads();
        int winner = tidxs[it];
        if (winner >= 0 && (winner & 255) == tid) {
            srow[winner] = NEGINF;
            m = NEGINF; mi = -1;
            for (int c = tid; c < BDIM; c += 256) { float vv2 = srow[c]; if (vv2 > m) { m = vv2; mi = c; } }
        }
        __syncthreads();
    }

    // rare exact-fp32 fixup when rank32/33 gap is within bf16x3 error reach
    bool need = (tvals[TOPK - 1] - tvals[TOPK]) < 1e-5f;
    if (need) {
        const float* hrow = hs + (size_t)row * HDIM;
        float inr = g_invn[row];
        for (int c = wid; c < CAND; c += 8) {
            int idx = tidxs[c];
            float e;
            if (idx < 0 || !isfinite(tvals[c])) {
                e = NEGINF;
            } else {
                const float* hc = hs + (size_t)idx * HDIM;
                float d = 0.f;
                for (int q = lid; q < HDIM; q += 32) d = fmaf(hrow[q], hc[q], d);
                #pragma unroll
                for (int o = 16; o; o >>= 1) d += __shfl_down_sync(0xffffffffu, d, o);
                e = d * inr * g_invn[idx];
            }
            if (lid == 0) exv[c] = e;
        }
        __syncthreads();
        if (tid == 0) {
            float fv[TOPK]; int fi[TOPK];
            bool used[CAND];
            for (int c = 0; c < CAND; c++) used[c] = false;
            for (int it = 0; it < TOPK; it++) {
                float bv = NEGINF; int bc = -1;
                for (int c = 0; c < CAND; c++)
                    if (!used[c] && (bc < 0 || exv[c] > bv)) { bv = exv[c]; bc = c; }
                used[bc] = true;
                fv[it] = bv; fi[it] = tidxs[bc];
            }
            for (int it = 0; it < TOPK; it++) { tvals[it] = fv[it]; tidxs[it] = fi[it]; }
        }
        __syncthreads();
    }

    if (tid < TOPK) {
        float mm = tvals[0];
        float v = tvals[tid];
        float e = (isfinite(v) && isfinite(mm)) ? __expf(v - mm) : 0.f;
        float s = e;
        for (int o = 16; o; o >>= 1) s += __shfl_down_sync(0xffffffffu, s, o);
        s = __shfl_sync(0xffffffffu, s, 0);
        float w = (s > 0.f) ? e / s : 0.f;
        g_topw[row * TOPK + tid] = w;
        g_topidx[row * TOPK + tid] = (tidxs[tid] >= 0) ? tidxs[tid] : 0;
    }
}

// ==================== K4: sparse cross + gate + residual ====================
__global__ __launch_bounds__(256) void cross_gate_kernel(const float* __restrict__ hs,
                                                         const float* __restrict__ gw,
                                                         const float* __restrict__ gb,
                                                         float* __restrict__ out) {
    const int row = blockIdx.x;
    const int tid = threadIdx.x;
    __shared__ float sw[TOPK];
    __shared__ int   si[TOPK];
    __shared__ float red[8];
    __shared__ float gsh;
    if (tid < TOPK) { sw[tid] = g_topw[row * TOPK + tid]; si[tid] = g_topidx[row * TOPK + tid]; }
    __syncthreads();

    float cr[HDIM / 256];
    float p = 0.f;
    #pragma unroll
    for (int u = 0; u < HDIM / 256; u++) {
        int c = tid + u * 256;
        float acc = 0.f;
        #pragma unroll
        for (int k = 0; k < TOPK; k++)
            acc = fmaf(sw[k], hs[(size_t)si[k] * HDIM + c], acc);
        cr[u] = acc;
        float h = hs[(size_t)row * HDIM + c];
        p = fmaf(gw[c], h, p);
        p = fmaf(gw[HDIM + c], acc, p);
    }
    for (int o = 16; o; o >>= 1) p += __shfl_down_sync(0xffffffffu, p, o);
    if ((tid & 31) == 0) red[tid >> 5] = p;
    __syncthreads();
    if (tid == 0) {
        float v = 0.f;
        for (int i = 0; i < 8; i++) v += red[i];
        gsh = 1.f / (1.f + __expf(-(v + gb[0])));
    }
    __syncthreads();
    float g = gsh;
    #pragma unroll
    for (int u = 0; u < HDIM / 256; u++) {
        int c = tid + u * 256;
        float h = hs[(size_t)row * HDIM + c];
        out[(size_t)row * HDIM + c] = h + g * cr[u];
    }
}

// ==================== launch ====================
extern "C" void kernel_launch(void* const* d_in, const int* in_sizes, int n_in,
                              void* d_out, int out_size) {
    const float* hs  = (const float*)d_in[0];
    const int*   msk = (const int*)d_in[1];
    const float* gw  = (const float*)d_in[2];
    const float* gb  = (const float*)d_in[3];
    float* out       = (float*)d_out;

    static int smem_set = 0;
    if (!smem_set) {
        cudaFuncSetAttribute(simgemm_mma, cudaFuncAttributeMaxDynamicSharedMemorySize, SMEM_TOTAL);
        smem_set = 1;
    }

    norms_kernel<<<BDIM, 256>>>(hs);
    prep_kernel<<<(BDIM * (HDIM / 4)) / 256, 256>>>(hs);
    dim3 grid(NRB, NRB);
    simgemm_mma<<<grid, 256, SMEM_TOTAL>>>(msk);
    topk_kernel<<<BDIM, 256>>>(hs);
    cross_gate_kernel<<<BDIM, 256>>>(hs, gw, gb, out);
}

// round 6
// speedup vs baseline: 4.1477x; 1.2115x over previous
#include <cuda_runtime.h>
#include <cuda_fp16.h>
#include <math.h>
#include <stdint.h>

#define BDIM 8192
#define HDIM 2048
#define TOPK 32
#define CAND 48
#define NEGINF (-INFINITY)

// ---- GEMM tiling ----
#define KCHUNK 64                          // fp16 per K-chunk = 128B rows (swizzle atom)
#define NKC (HDIM / KCHUNK)                // 32
#define TILE_M 128
#define NRB (BDIM / TILE_M)                // 64
#define TILE_ELEMS (TILE_M * KCHUNK)       // 8192 fp16
#define TILE_BYTES (TILE_ELEMS * 2)        // 16384
#define STAGES 3
#define STAGE_BYTES (2 * TILE_BYTES)       // 32768 (A, B)
#define SMEM_TOTAL (STAGES * STAGE_BYTES)  // 98304

// ---- device scratch ----
__device__ float g_sim[(size_t)BDIM * BDIM];     // 256 MB
__device__ float g_invn[BDIM];
__device__ int   g_topidx[BDIM * TOPK];
__device__ float g_topw[BDIM * TOPK];
__device__ __half g_hi[(size_t)NKC * NRB * TILE_ELEMS];   // 32 MB pre-swizzled tiles

// ==================== asm helpers ====================
__device__ __forceinline__ uint32_t smem_u32(const void* p) {
    uint32_t a;
    asm("{ .reg .u64 t; cvta.to.shared.u64 t, %1; cvt.u32.u64 %0, t; }" : "=r"(a) : "l"(p));
    return a;
}

#define CP16(dst, src) \
    asm volatile("cp.async.cg.shared.global [%0], [%1], 16;" :: "r"(dst), "l"(src) : "memory")
#define CPCOMMIT() asm volatile("cp.async.commit_group;" ::: "memory")
#define CPWAIT1()  asm volatile("cp.async.wait_group 1;" ::: "memory")
#define CPWAIT0()  asm volatile("cp.async.wait_group 0;" ::: "memory")

#define LDSM4(r0, r1, r2, r3, addr) \
    asm volatile("ldmatrix.sync.aligned.m8n8.x4.shared.b16 {%0,%1,%2,%3}, [%4];" \
        : "=r"(r0), "=r"(r1), "=r"(r2), "=r"(r3) : "r"(addr))

#define MMA16816(d, a, b) \
    asm volatile("mma.sync.aligned.m16n8k16.row.col.f32.f16.f16.f32 " \
        "{%0,%1,%2,%3}, {%4,%5,%6,%7}, {%8,%9}, {%0,%1,%2,%3};" \
        : "+f"((d)[0]), "+f"((d)[1]), "+f"((d)[2]), "+f"((d)[3]) \
        : "r"((a)[0]), "r"((a)[1]), "r"((a)[2]), "r"((a)[3]), "r"((b)[0]), "r"((b)[1]))

// ==================== K0: inverse row norms ====================
__global__ __launch_bounds__(256) void norms_kernel(const float* __restrict__ hs) {
    int row = blockIdx.x;
    const float* p = hs + (size_t)row * HDIM;
    float s = 0.f;
    for (int c = threadIdx.x; c < HDIM; c += 256) { float v = p[c]; s += v * v; }
    __shared__ float red[8];
    for (int o = 16; o; o >>= 1) s += __shfl_down_sync(0xffffffffu, s, o);
    if ((threadIdx.x & 31) == 0) red[threadIdx.x >> 5] = s;
    __syncthreads();
    if (threadIdx.x == 0) {
        float v = 0.f;
        for (int i = 0; i < 8; i++) v += red[i];
        g_invn[row] = 1.0f / fmaxf(sqrtf(v), 1e-12f);
    }
}

// ==================== K1: fp16 pre-swizzled tiles ====================
__global__ __launch_bounds__(256) void prep_kernel(const float* __restrict__ hs) {
    size_t i4 = (size_t)blockIdx.x * 256 + threadIdx.x;
    int r  = (int)(i4 / (HDIM / 4));
    int k4 = (int)(i4 % (HDIM / 4)) * 4;
    float4 v = *(const float4*)(hs + (size_t)r * HDIM + k4);
    float vv[4] = {v.x, v.y, v.z, v.w};
    int kc = k4 >> 6;
    int rb = r >> 7, rr = r & 127;
    size_t base = ((size_t)(kc * NRB + rb)) * TILE_ELEMS;
    #pragma unroll
    for (int j = 0; j < 4; j++) {
        int c = (k4 + j) & 63;
        uint32_t off = (uint32_t)(rr * 128 + c * 2);
        uint32_t sw  = (off ^ (((uint32_t)(rr & 7)) << 4)) >> 1;
        g_hi[base + sw] = __float2half(vv[j]);
    }
}

// ==================== K2: sim ~= H H^T via fp16 mma.sync, symmetric ====================
__global__ __launch_bounds__(256, 2) void simgemm_mma(const int* __restrict__ mask) {
    const int bj = blockIdx.x, bi = blockIdx.y;
    if (bi > bj) return;
    extern __shared__ __align__(128) char smem[];
    const uint32_t sbase = smem_u32(smem);
    const int tid = threadIdx.x;
    const int lane = tid & 31, wid = tid >> 5;
    const int wm = wid & 1, wn = wid >> 1;

    float acc[4][4][4];
    #pragma unroll
    for (int a = 0; a < 4; a++)
        #pragma unroll
        for (int b = 0; b < 4; b++)
            #pragma unroll
            for (int c = 0; c < 4; c++) acc[a][b][c] = 0.f;

    const __half* baseA = g_hi + (size_t)bi * TILE_ELEMS;
    const __half* baseB = g_hi + (size_t)bj * TILE_ELEMS;
    const size_t kc_stride = (size_t)NRB * TILE_ELEMS;

    const int rbase = (lane & 7) + ((lane >> 3) & 1) * 8;
    const int csel  = lane >> 4;

    auto issue = [&](int kc, int s) {
        uint32_t sb = sbase + s * STAGE_BYTES;
        const char* sa  = (const char*)(baseA + (size_t)kc * kc_stride);
        const char* sbp = (const char*)(baseB + (size_t)kc * kc_stride);
        #pragma unroll
        for (int i = 0; i < 4; i++) {
            uint32_t o = (uint32_t)(tid * 16 + i * 4096);
            CP16(sb + o, sa + o);
            CP16(sb + TILE_BYTES + o, sbp + o);
        }
        CPCOMMIT();
    };

    issue(0, 0);
    issue(1, 1);

    for (int kc = 0; kc < NKC; kc++) {
        CPWAIT1();
        __syncthreads();
        if (kc + 2 < NKC) issue(kc + 2, (kc + 2) % STAGES);

        uint32_t sb = sbase + (kc % STAGES) * STAGE_BYTES;
        #pragma unroll
        for (int k16 = 0; k16 < 4; k16++) {
            uint32_t ah[4][4], bh[4][2];
            #pragma unroll
            for (int mt = 0; mt < 4; mt++) {
                int row = wm * 64 + mt * 16 + rbase;
                uint32_t off = (uint32_t)(row * 128 + (((k16 * 2 + csel) ^ (row & 7)) * 16));
                LDSM4(ah[mt][0], ah[mt][1], ah[mt][2], ah[mt][3], sb + off);
            }
            #pragma unroll
            for (int p = 0; p < 2; p++) {
                int row = wn * 32 + p * 16 + rbase;
                uint32_t off = (uint32_t)(row * 128 + (((k16 * 2 + csel) ^ (row & 7)) * 16));
                uint32_t r0, r1, r2, r3;
                LDSM4(r0, r1, r2, r3, sb + TILE_BYTES + off);
                bh[2*p][0] = r0; bh[2*p][1] = r2; bh[2*p+1][0] = r1; bh[2*p+1][1] = r3;
            }
            #pragma unroll
            for (int mt = 0; mt < 4; mt++)
                #pragma unroll
                for (int nt = 0; nt < 4; nt++)
                    MMA16816(acc[mt][nt], ah[mt], bh[nt]);
        }
    }
    CPWAIT0();

    // ---- epilogue ----
    const int i0 = bi * 128 + wm * 64;
    const int j0 = bj * 128 + wn * 32;
    const int grp = lane >> 2, qd = lane & 3;
    #pragma unroll
    for (int mt = 0; mt < 4; mt++) {
        #pragma unroll
        for (int half = 0; half < 2; half++) {
            int row = i0 + mt * 16 + grp + half * 8;
            float sa = g_invn[row];
            int mr = mask[row];
            #pragma unroll
            for (int nt = 0; nt < 4; nt++) {
                int col = j0 + nt * 8 + qd * 2;
                float v0 = acc[mt][nt][half * 2 + 0] * sa * g_invn[col];
                float v1 = acc[mt][nt][half * 2 + 1] * sa * g_invn[col + 1];
                float2 o;
                o.x = (row == col     || mask[col]     == 0) ? NEGINF : v0;
                o.y = (row == col + 1 || mask[col + 1] == 0) ? NEGINF : v1;
                *(float2*)(g_sim + (size_t)row * BDIM + col) = o;
                if (bi != bj) {
                    g_sim[(size_t)col * BDIM + row]       = mr ? v0 : NEGINF;
                    g_sim[(size_t)(col + 1) * BDIM + row] = mr ? v1 : NEGINF;
                }
            }
        }
    }
}

// ==================== K3: per-row top-32 (warp lists + merge + exact fixup) ====================
__global__ __launch_bounds__(256) void topk_kernel(const float* __restrict__ hs) {
    __shared__ float srow[BDIM];                 // 32 KB
    __shared__ float wval[8 * CAND];
    __shared__ int   widx[8 * CAND];
    __shared__ float tvals[CAND];
    __shared__ int   tidxs[CAND];
    __shared__ float exv[CAND];
    const int row = blockIdx.x;
    const int tid = threadIdx.x, wid = tid >> 5, lid = tid & 31;
    const float* sp = g_sim + (size_t)row * BDIM;

    for (int c = tid * 4; c < BDIM; c += 1024)
        *(float4*)(srow + c) = *(const float4*)(sp + c);
    __syncthreads();

    // phase 1: each warp builds a sorted top-CAND over its 1024-slice (no block syncs)
    {
        const int b0 = wid * 1024 + lid;
        float m = NEGINF; int mi = -1;
        #pragma unroll
        for (int t = 0; t < 32; t++) {
            int c = b0 + t * 32;
            float v = srow[c];
            if (v > m) { m = v; mi = c; }
        }
        for (int it = 0; it < CAND; it++) {
            float v = m; int x = mi;
            #pragma unroll
            for (int o = 16; o; o >>= 1) {
                float ov = __shfl_down_sync(0xffffffffu, v, o);
                int   ox = __shfl_down_sync(0xffffffffu, x, o);
                if (ov > v) { v = ov; x = ox; }
            }
            v = __shfl_sync(0xffffffffu, v, 0);
            x = __shfl_sync(0xffffffffu, x, 0);
            if (lid == 0) { wval[wid * CAND + it] = v; widx[wid * CAND + it] = x; }
            if (x == mi && x >= 0) {            // owner lane: remove + rescan slice
                srow[x] = NEGINF;
                m = NEGINF; mi = -1;
                #pragma unroll
                for (int t = 0; t < 32; t++) {
                    int c = b0 + t * 32;
                    float vv = srow[c];
                    if (vv > m) { m = vv; mi = c; }
                }
            }
        }
    }
    __syncthreads();

    // phase 2: warp 0 merges 8 sorted lists -> global top-CAND
    if (wid == 0) {
        int head = 0;
        float v = (lid < 8) ? wval[lid * CAND] : NEGINF;
        int   x = (lid < 8) ? widx[lid * CAND] : -1;
        for (int it = 0; it < CAND; it++) {
            float bv = v; int bl = lid;
            #pragma unroll
            for (int o = 16; o; o >>= 1) {
                float ov = __shfl_down_sync(0xffffffffu, bv, o);
                int   ol = __shfl_down_sync(0xffffffffu, bl, o);
                if (ov > bv) { bv = ov; bl = ol; }
            }
            bv = __shfl_sync(0xffffffffu, bv, 0);
            bl = __shfl_sync(0xffffffffu, bl, 0);
            int bx = __shfl_sync(0xffffffffu, x, bl);   // ALL lanes participate
            if (lid == 0) { tvals[it] = bv; tidxs[it] = bx; }
            if (lid == bl) {
                head++;
                v = (head < CAND) ? wval[lid * CAND + head] : NEGINF;
                x = (head < CAND) ? widx[lid * CAND + head] : -1;
            }
        }
    }
    __syncthreads();

    // exact-fp32 fixup when the rank32/33 gap is within fp16 error reach
    bool need = (tvals[TOPK - 1] - tvals[TOPK]) < 1e-4f;
    if (need) {
        const float* hrow = hs + (size_t)row * HDIM;
        float inr = g_invn[row];
        for (int c = wid; c < CAND; c += 8) {
            int idx = tidxs[c];
            float e;
            if (idx < 0 || !isfinite(tvals[c])) {
                e = NEGINF;
            } else {
                const float* hc = hs + (size_t)idx * HDIM;
                float d = 0.f;
                for (int q = lid; q < HDIM; q += 32) d = fmaf(hrow[q], hc[q], d);
                #pragma unroll
                for (int o = 16; o; o >>= 1) d += __shfl_down_sync(0xffffffffu, d, o);
                e = d * inr * g_invn[idx];
            }
            if (lid == 0) exv[c] = e;
        }
        __syncthreads();
        if (tid == 0) {
            float fv[TOPK]; int fi[TOPK];
            bool used[CAND];
            for (int c = 0; c < CAND; c++) used[c] = false;
            for (int it = 0; it < TOPK; it++) {
                float bv = NEGINF; int bc = -1;
                for (int c = 0; c < CAND; c++)
                    if (!used[c] && (bc < 0 || exv[c] > bv)) { bv = exv[c]; bc = c; }
                used[bc] = true;
                fv[it] = bv; fi[it] = tidxs[bc];
            }
            for (int it = 0; it < TOPK; it++) { tvals[it] = fv[it]; tidxs[it] = fi[it]; }
        }
        __syncthreads();
    }

    if (tid < TOPK) {
        float mm = tvals[0];
        float v = tvals[tid];
        float e = (isfinite(v) && isfinite(mm)) ? __expf(v - mm) : 0.f;
        float s = e;
        for (int o = 16; o; o >>= 1) s += __shfl_down_sync(0xffffffffu, s, o);
        s = __shfl_sync(0xffffffffu, s, 0);
        float w = (s > 0.f) ? e / s : 0.f;
        g_topw[row * TOPK + tid] = w;
        g_topidx[row * TOPK + tid] = (tidxs[tid] >= 0) ? tidxs[tid] : 0;
    }
}

// ==================== K4: sparse cross + gate + residual ====================
__global__ __launch_bounds__(256) void cross_gate_kernel(const float* __restrict__ hs,
                                                         const float* __restrict__ gw,
                                                         const float* __restrict__ gb,
                                                         float* __restrict__ out) {
    const int row = blockIdx.x;
    const int tid = threadIdx.x;
    __shared__ float sw[TOPK];
    __shared__ int   si[TOPK];
    __shared__ float red[8];
    __shared__ float gsh;
    if (tid < TOPK) { sw[tid] = g_topw[row * TOPK + tid]; si[tid] = g_topidx[row * TOPK + tid]; }
    __syncthreads();

    float cr[HDIM / 256];
    float p = 0.f;
    #pragma unroll
    for (int u = 0; u < HDIM / 256; u++) {
        int c = tid + u * 256;
        float acc = 0.f;
        #pragma unroll
        for (int k = 0; k < TOPK; k++)
            acc = fmaf(sw[k], hs[(size_t)si[k] * HDIM + c], acc);
        cr[u] = acc;
        float h = hs[(size_t)row * HDIM + c];
        p = fmaf(gw[c], h, p);
        p = fmaf(gw[HDIM + c], acc, p);
    }
    for (int o = 16; o; o >>= 1) p += __shfl_down_sync(0xffffffffu, p, o);
    if ((tid & 31) == 0) red[tid >> 5] = p;
    __syncthreads();
    if (tid == 0) {
        float v = 0.f;
        for (int i = 0; i < 8; i++) v += red[i];
        gsh = 1.f / (1.f + __expf(-(v + gb[0])));
    }
    __syncthreads();
    float g = gsh;
    #pragma unroll
    for (int u = 0; u < HDIM / 256; u++) {
        int c = tid + u * 256;
        float h = hs[(size_t)row * HDIM + c];
        out[(size_t)row * HDIM + c] = h + g * cr[u];
    }
}

// ==================== launch ====================
extern "C" void kernel_launch(void* const* d_in, const int* in_sizes, int n_in,
                              void* d_out, int out_size) {
    const float* hs  = (const float*)d_in[0];
    const int*   msk = (const int*)d_in[1];
    const float* gw  = (const float*)d_in[2];
    const float* gb  = (const float*)d_in[3];
    float* out       = (float*)d_out;

    static int smem_set = 0;
    if (!smem_set) {
        cudaFuncSetAttribute(simgemm_mma, cudaFuncAttributeMaxDynamicSharedMemorySize, SMEM_TOTAL);
        smem_set = 1;
    }

    norms_kernel<<<BDIM, 256>>>(hs);
    prep_kernel<<<(BDIM * (HDIM / 4)) / 256, 256>>>(hs);
    dim3 grid(NRB, NRB);
    simgemm_mma<<<grid, 256, SMEM_TOTAL>>>(msk);
    topk_kernel<<<BDIM, 256>>>(hs);
    cross_gate_kernel<<<BDIM, 256>>>(hs, gw, gb, out);
}

// round 7
// speedup vs baseline: 5.1354x; 1.2381x over previous
#include <cuda_runtime.h>
#include <cuda_fp16.h>
#include <math.h>
#include <stdint.h>

#define BDIM 8192
#define HDIM 2048
#define TOPK 32
#define CAND 48
#define NCAP 96
#define NEGINF (-INFINITY)

// ---- GEMM tiling ----
#define KCHUNK 64
#define NKC (HDIM / KCHUNK)
#define TILE_M 128
#define NRB (BDIM / TILE_M)
#define TILE_ELEMS (TILE_M * KCHUNK)
#define TILE_BYTES (TILE_ELEMS * 2)
#define STAGES 3
#define STAGE_BYTES (2 * TILE_BYTES)
#define SMEM_TOTAL (STAGES * STAGE_BYTES)

// ---- device scratch ----
__device__ float g_sim[(size_t)BDIM * BDIM];
__device__ float g_invn[BDIM];
__device__ int   g_topidx[BDIM * TOPK];
__device__ float g_topw[BDIM * TOPK];
__device__ __half g_hi[(size_t)NKC * NRB * TILE_ELEMS];

// ==================== asm helpers ====================
__device__ __forceinline__ uint32_t smem_u32(const void* p) {
    uint32_t a;
    asm("{ .reg .u64 t; cvta.to.shared.u64 t, %1; cvt.u32.u64 %0, t; }" : "=r"(a) : "l"(p));
    return a;
}

#define CP16(dst, src) \
    asm volatile("cp.async.cg.shared.global [%0], [%1], 16;" :: "r"(dst), "l"(src) : "memory")
#define CPCOMMIT() asm volatile("cp.async.commit_group;" ::: "memory")
#define CPWAIT1()  asm volatile("cp.async.wait_group 1;" ::: "memory")
#define CPWAIT0()  asm volatile("cp.async.wait_group 0;" ::: "memory")

#define LDSM4(r0, r1, r2, r3, addr) \
    asm volatile("ldmatrix.sync.aligned.m8n8.x4.shared.b16 {%0,%1,%2,%3}, [%4];" \
        : "=r"(r0), "=r"(r1), "=r"(r2), "=r"(r3) : "r"(addr))

#define MMA16816(d, a, b) \
    asm volatile("mma.sync.aligned.m16n8k16.row.col.f32.f16.f16.f32 " \
        "{%0,%1,%2,%3}, {%4,%5,%6,%7}, {%8,%9}, {%0,%1,%2,%3};" \
        : "+f"((d)[0]), "+f"((d)[1]), "+f"((d)[2]), "+f"((d)[3]) \
        : "r"((a)[0]), "r"((a)[1]), "r"((a)[2]), "r"((a)[3]), "r"((b)[0]), "r"((b)[1]))

// ==================== K0: inverse row norms ====================
__global__ __launch_bounds__(256) void norms_kernel(const float* __restrict__ hs) {
    int row = blockIdx.x;
    const float* p = hs + (size_t)row * HDIM;
    float s = 0.f;
    for (int c = threadIdx.x; c < HDIM; c += 256) { float v = p[c]; s += v * v; }
    __shared__ float red[8];
    for (int o = 16; o; o >>= 1) s += __shfl_down_sync(0xffffffffu, s, o);
    if ((threadIdx.x & 31) == 0) red[threadIdx.x >> 5] = s;
    __syncthreads();
    if (threadIdx.x == 0) {
        float v = 0.f;
        for (int i = 0; i < 8; i++) v += red[i];
        g_invn[row] = 1.0f / fmaxf(sqrtf(v), 1e-12f);
    }
}

// ==================== K1: fp16 pre-swizzled tiles ====================
__global__ __launch_bounds__(256) void prep_kernel(const float* __restrict__ hs) {
    size_t i4 = (size_t)blockIdx.x * 256 + threadIdx.x;
    int r  = (int)(i4 / (HDIM / 4));
    int k4 = (int)(i4 % (HDIM / 4)) * 4;
    float4 v = *(const float4*)(hs + (size_t)r * HDIM + k4);
    float vv[4] = {v.x, v.y, v.z, v.w};
    int kc = k4 >> 6;
    int rb = r >> 7, rr = r & 127;
    size_t base = ((size_t)(kc * NRB + rb)) * TILE_ELEMS;
    #pragma unroll
    for (int j = 0; j < 4; j++) {
        int c = (k4 + j) & 63;
        uint32_t off = (uint32_t)(rr * 128 + c * 2);
        uint32_t sw  = (off ^ (((uint32_t)(rr & 7)) << 4)) >> 1;
        g_hi[base + sw] = __float2half(vv[j]);
    }
}

// ==================== K2: sim ~= H H^T via fp16 mma.sync, symmetric ====================
__global__ __launch_bounds__(256, 2) void simgemm_mma(const int* __restrict__ mask) {
    const int bj = blockIdx.x, bi = blockIdx.y;
    if (bi > bj) return;
    extern __shared__ __align__(128) char smem[];
    const uint32_t sbase = smem_u32(smem);
    const int tid = threadIdx.x;
    const int lane = tid & 31, wid = tid >> 5;
    const int wm = wid & 1, wn = wid >> 1;

    float acc[4][4][4];
    #pragma unroll
    for (int a = 0; a < 4; a++)
        #pragma unroll
        for (int b = 0; b < 4; b++)
            #pragma unroll
            for (int c = 0; c < 4; c++) acc[a][b][c] = 0.f;

    const __half* baseA = g_hi + (size_t)bi * TILE_ELEMS;
    const __half* baseB = g_hi + (size_t)bj * TILE_ELEMS;
    const size_t kc_stride = (size_t)NRB * TILE_ELEMS;

    const int rbase = (lane & 7) + ((lane >> 3) & 1) * 8;
    const int csel  = lane >> 4;

    auto issue = [&](int kc, int s) {
        uint32_t sb = sbase + s * STAGE_BYTES;
        const char* sa  = (const char*)(baseA + (size_t)kc * kc_stride);
        const char* sbp = (const char*)(baseB + (size_t)kc * kc_stride);
        #pragma unroll
        for (int i = 0; i < 4; i++) {
            uint32_t o = (uint32_t)(tid * 16 + i * 4096);
            CP16(sb + o, sa + o);
            CP16(sb + TILE_BYTES + o, sbp + o);
        }
        CPCOMMIT();
    };

    issue(0, 0);
    issue(1, 1);

    for (int kc = 0; kc < NKC; kc++) {
        CPWAIT1();
        __syncthreads();
        if (kc + 2 < NKC) issue(kc + 2, (kc + 2) % STAGES);

        uint32_t sb = sbase + (kc % STAGES) * STAGE_BYTES;
        #pragma unroll
        for (int k16 = 0; k16 < 4; k16++) {
            uint32_t ah[4][4], bh[4][2];
            #pragma unroll
            for (int mt = 0; mt < 4; mt++) {
                int row = wm * 64 + mt * 16 + rbase;
                uint32_t off = (uint32_t)(row * 128 + (((k16 * 2 + csel) ^ (row & 7)) * 16));
                LDSM4(ah[mt][0], ah[mt][1], ah[mt][2], ah[mt][3], sb + off);
            }
            #pragma unroll
            for (int p = 0; p < 2; p++) {
                int row = wn * 32 + p * 16 + rbase;
                uint32_t off = (uint32_t)(row * 128 + (((k16 * 2 + csel) ^ (row & 7)) * 16));
                uint32_t r0, r1, r2, r3;
                LDSM4(r0, r1, r2, r3, sb + TILE_BYTES + off);
                bh[2*p][0] = r0; bh[2*p][1] = r2; bh[2*p+1][0] = r1; bh[2*p+1][1] = r3;
            }
            #pragma unroll
            for (int mt = 0; mt < 4; mt++)
                #pragma unroll
                for (int nt = 0; nt < 4; nt++)
                    MMA16816(acc[mt][nt], ah[mt], bh[nt]);
        }
    }
    CPWAIT0();

    const int i0 = bi * 128 + wm * 64;
    const int j0 = bj * 128 + wn * 32;
    const int grp = lane >> 2, qd = lane & 3;
    #pragma unroll
    for (int mt = 0; mt < 4; mt++) {
        #pragma unroll
        for (int half = 0; half < 2; half++) {
            int row = i0 + mt * 16 + grp + half * 8;
            float sa = g_invn[row];
            int mr = mask[row];
            #pragma unroll
            for (int nt = 0; nt < 4; nt++) {
                int col = j0 + nt * 8 + qd * 2;
                float v0 = acc[mt][nt][half * 2 + 0] * sa * g_invn[col];
                float v1 = acc[mt][nt][half * 2 + 1] * sa * g_invn[col + 1];
                float2 o;
                o.x = (row == col     || mask[col]     == 0) ? NEGINF : v0;
                o.y = (row == col + 1 || mask[col + 1] == 0) ? NEGINF : v1;
                *(float2*)(g_sim + (size_t)row * BDIM + col) = o;
                if (bi != bj) {
                    g_sim[(size_t)col * BDIM + row]       = mr ? v0 : NEGINF;
                    g_sim[(size_t)(col + 1) * BDIM + row] = mr ? v1 : NEGINF;
                }
            }
        }
    }
}

// ==================== K3: per-row top-32 via radix select ====================
__global__ __launch_bounds__(256) void topk_kernel(const float* __restrict__ hs) {
    __shared__ uint32_t skey[BDIM];              // 32 KB
    __shared__ int hist[256];
    __shared__ int sbin, srem, scnt;
    __shared__ float cval[NCAP];
    __shared__ int   cidx[NCAP];
    __shared__ float svals[NCAP];
    __shared__ int   sidxs[NCAP];
    __shared__ float exv[CAND];
    const int row = blockIdx.x;
    const int tid = threadIdx.x, wid = tid >> 5, lid = tid & 31;
    const float* sp = g_sim + (size_t)row * BDIM;

    // load + order-preserving transform: larger float -> larger uint
    for (int c = tid * 4; c < BDIM; c += 1024) {
        float4 v = *(const float4*)(sp + c);
        const float* vp = &v.x;
        #pragma unroll
        for (int j = 0; j < 4; j++) {
            uint32_t b = __float_as_uint(vp[j]);
            skey[c + j] = (b & 0x80000000u) ? ~b : (b | 0x80000000u);
        }
    }
    __syncthreads();

    // ---- 4-level radix select: find exact CAND-th largest key ----
    uint32_t prefix = 0;
    int rem = CAND;
    #pragma unroll
    for (int shift = 24; shift >= 0; shift -= 8) {
        hist[tid] = 0;
        __syncthreads();
        uint32_t pmask = (shift == 24) ? 0u : (0xFFFFFFFFu << (shift + 8));
        for (int c = tid; c < BDIM; c += 256) {
            uint32_t k = skey[c];
            bool part = (k & pmask) == prefix;
            uint32_t bin = part ? ((k >> shift) & 255u) : 0xFFFFFFFFu;
            uint32_t mgrp = __match_any_sync(0xFFFFFFFFu, bin);
            int leader = __ffs(mgrp) - 1;
            if (part && lid == leader) atomicAdd(&hist[bin], __popc(mgrp));
        }
        __syncthreads();
        if (tid < 32) {
            int b0 = 248 - 8 * tid;             // lane 0 covers highest bins 248..255
            int h[8], part = 0;
            #pragma unroll
            for (int q = 0; q < 8; q++) { h[q] = hist[b0 + q]; part += h[q]; }
            int inc = part;
            #pragma unroll
            for (int o = 1; o < 32; o <<= 1) {
                int t = __shfl_up_sync(0xffffffffu, inc, o);
                if (tid >= o) inc += t;
            }
            int pre = inc - part;               // count of keys in strictly-higher groups
            if (pre < rem && rem <= inc) {
                int c = pre;
                #pragma unroll
                for (int q = 7; q >= 0; q--) {
                    int nb = c + h[q];
                    if (nb >= rem) { sbin = b0 + q; srem = rem - c; break; }
                    c = nb;
                }
            }
        }
        __syncthreads();
        prefix |= ((uint32_t)sbin) << shift;
        rem = srem;
        __syncthreads();
    }

    // ---- gather candidates (key >= threshold key) ----
    if (tid == 0) scnt = 0;
    __syncthreads();
    for (int c = tid; c < BDIM; c += 256) {
        uint32_t k = skey[c];
        if (k >= prefix) {
            int p = atomicAdd(&scnt, 1);
            if (p < NCAP) {
                cidx[p] = c;
                uint32_t b = (k & 0x80000000u) ? (k & 0x7FFFFFFFu) : ~k;
                cval[p] = __uint_as_float(b);
            }
        }
    }
    __syncthreads();
    int n = (scnt < NCAP) ? scnt : NCAP;

    // ---- rank sort descending (stable by index) ----
    if (tid < n) {
        float v = cval[tid]; int ix = cidx[tid];
        int r = 0;
        for (int j = 0; j < n; j++) {
            float vj = cval[j];
            if (vj > v || (vj == v && cidx[j] < ix)) r++;
        }
        svals[r] = v; sidxs[r] = ix;
    }
    __syncthreads();

    // ---- exact-fp32 fixup when rank32/33 gap is within fp16 error reach ----
    bool need = (svals[TOPK - 1] - svals[TOPK]) < 1e-4f;
    if (need) {
        const float* hrow = hs + (size_t)row * HDIM;
        float inr = g_invn[row];
        for (int c = wid; c < CAND; c += 8) {
            int idx = sidxs[c];
            const float* hc = hs + (size_t)idx * HDIM;
            float d = 0.f;
            for (int q = lid; q < HDIM; q += 32) d = fmaf(hrow[q], hc[q], d);
            #pragma unroll
            for (int o = 16; o; o >>= 1) d += __shfl_down_sync(0xffffffffu, d, o);
            if (lid == 0) exv[c] = d * inr * g_invn[idx];
        }
        __syncthreads();
        if (tid == 0) {
            float fv[TOPK]; int fi[TOPK];
            bool used[CAND];
            for (int c = 0; c < CAND; c++) used[c] = false;
            for (int it = 0; it < TOPK; it++) {
                float bv = NEGINF; int bc = -1;
                for (int c = 0; c < CAND; c++)
                    if (!used[c] && (bc < 0 || exv[c] > bv)) { bv = exv[c]; bc = c; }
                used[bc] = true;
                fv[it] = bv; fi[it] = sidxs[bc];
            }
            for (int it = 0; it < TOPK; it++) { svals[it] = fv[it]; sidxs[it] = fi[it]; }
        }
        __syncthreads();
    }

    // ---- softmax over top-32 ----
    if (tid < TOPK) {
        float mm = svals[0];
        float v = svals[tid];
        float e = (isfinite(v) && isfinite(mm)) ? __expf(v - mm) : 0.f;
        float s = e;
        for (int o = 16; o; o >>= 1) s += __shfl_down_sync(0xffffffffu, s, o);
        s = __shfl_sync(0xffffffffu, s, 0);
        float w = (s > 0.f) ? e / s : 0.f;
        g_topw[row * TOPK + tid] = w;
        g_topidx[row * TOPK + tid] = sidxs[tid];
    }
}

// ==================== K4: sparse cross + gate + residual ====================
__global__ __launch_bounds__(256) void cross_gate_kernel(const float* __restrict__ hs,
                                                         const float* __restrict__ gw,
                                                         const float* __restrict__ gb,
                                                         float* __restrict__ out) {
    const int row = blockIdx.x;
    const int tid = threadIdx.x;
    __shared__ float sw[TOPK];
    __shared__ int   si[TOPK];
    __shared__ float red[8];
    __shared__ float gsh;
    if (tid < TOPK) { sw[tid] = g_topw[row * TOPK + tid]; si[tid] = g_topidx[row * TOPK + tid]; }
    __syncthreads();

    float cr[HDIM / 256];
    float p = 0.f;
    #pragma unroll
    for (int u = 0; u < HDIM / 256; u++) {
        int c = tid + u * 256;
        float acc = 0.f;
        #pragma unroll
        for (int k = 0; k < TOPK; k++)
            acc = fmaf(sw[k], hs[(size_t)si[k] * HDIM + c], acc);
        cr[u] = acc;
        float h = hs[(size_t)row * HDIM + c];
        p = fmaf(gw[c], h, p);
        p = fmaf(gw[HDIM + c], acc, p);
    }
    for (int o = 16; o; o >>= 1) p += __shfl_down_sync(0xffffffffu, p, o);
    if ((tid & 31) == 0) red[tid >> 5] = p;
    __syncthreads();
    if (tid == 0) {
        float v = 0.f;
        for (int i = 0; i < 8; i++) v += red[i];
        gsh = 1.f / (1.f + __expf(-(v + gb[0])));
    }
    __syncthreads();
    float g = gsh;
    #pragma unroll
    for (int u = 0; u < HDIM / 256; u++) {
        int c = tid + u * 256;
        float h = hs[(size_t)row * HDIM + c];
        out[(size_t)row * HDIM + c] = h + g * cr[u];
    }
}

// ==================== launch ====================
extern "C" void kernel_launch(void* const* d_in, const int* in_sizes, int n_in,
                              void* d_out, int out_size) {
    const float* hs  = (const float*)d_in[0];
    const int*   msk = (const int*)d_in[1];
    const float* gw  = (const float*)d_in[2];
    const float* gb  = (const float*)d_in[3];
    float* out       = (float*)d_out;

    static int smem_set = 0;
    if (!smem_set) {
        cudaFuncSetAttribute(simgemm_mma, cudaFuncAttributeMaxDynamicSharedMemorySize, SMEM_TOTAL);
        smem_set = 1;
    }

    norms_kernel<<<BDIM, 256>>>(hs);
    prep_kernel<<<(BDIM * (HDIM / 4)) / 256, 256>>>(hs);
    dim3 grid(NRB, NRB);
    simgemm_mma<<<grid, 256, SMEM_TOTAL>>>(msk);
    topk_kernel<<<BDIM, 256>>>(hs);
    cross_gate_kernel<<<BDIM, 256>>>(hs, gw, gb, out);
}

// round 8
// speedup vs baseline: 5.5082x; 1.0726x over previous
#include <cuda_runtime.h>
#include <cuda_fp16.h>
#include <math.h>
#include <stdint.h>

#define BDIM 8192
#define HDIM 2048
#define TOPK 32
#define CAND 48
#define LCAP 3072
#define FCAP 128
#define NEGINF (-INFINITY)

// ---- GEMM tiling ----
#define KCHUNK 64
#define NKC (HDIM / KCHUNK)
#define TILE_M 128
#define NRB (BDIM / TILE_M)
#define TILE_ELEMS (TILE_M * KCHUNK)
#define TILE_BYTES (TILE_ELEMS * 2)
#define STAGES 3
#define STAGE_BYTES (2 * TILE_BYTES)
#define SMEM_TOTAL (STAGES * STAGE_BYTES)

// ---- device scratch ----
__device__ float g_sim[(size_t)BDIM * BDIM];
__device__ float g_invn[BDIM];
__device__ int   g_topidx[BDIM * TOPK];
__device__ float g_topw[BDIM * TOPK];
__device__ __half g_hi[(size_t)NKC * NRB * TILE_ELEMS];

// ==================== asm helpers ====================
__device__ __forceinline__ uint32_t smem_u32(const void* p) {
    uint32_t a;
    asm("{ .reg .u64 t; cvta.to.shared.u64 t, %1; cvt.u32.u64 %0, t; }" : "=r"(a) : "l"(p));
    return a;
}

#define CP16(dst, src) \
    asm volatile("cp.async.cg.shared.global [%0], [%1], 16;" :: "r"(dst), "l"(src) : "memory")
#define CPCOMMIT() asm volatile("cp.async.commit_group;" ::: "memory")
#define CPWAIT1()  asm volatile("cp.async.wait_group 1;" ::: "memory")
#define CPWAIT0()  asm volatile("cp.async.wait_group 0;" ::: "memory")

#define LDSM4(r0, r1, r2, r3, addr) \
    asm volatile("ldmatrix.sync.aligned.m8n8.x4.shared.b16 {%0,%1,%2,%3}, [%4];" \
        : "=r"(r0), "=r"(r1), "=r"(r2), "=r"(r3) : "r"(addr))

#define MMA16816(d, a, b) \
    asm volatile("mma.sync.aligned.m16n8k16.row.col.f32.f16.f16.f32 " \
        "{%0,%1,%2,%3}, {%4,%5,%6,%7}, {%8,%9}, {%0,%1,%2,%3};" \
        : "+f"((d)[0]), "+f"((d)[1]), "+f"((d)[2]), "+f"((d)[3]) \
        : "r"((a)[0]), "r"((a)[1]), "r"((a)[2]), "r"((a)[3]), "r"((b)[0]), "r"((b)[1]))

// ==================== K0: inverse row norms ====================
__global__ __launch_bounds__(256) void norms_kernel(const float* __restrict__ hs) {
    int row = blockIdx.x;
    const float* p = hs + (size_t)row * HDIM;
    float s = 0.f;
    for (int c = threadIdx.x; c < HDIM; c += 256) { float v = p[c]; s += v * v; }
    __shared__ float red[8];
    for (int o = 16; o; o >>= 1) s += __shfl_down_sync(0xffffffffu, s, o);
    if ((threadIdx.x & 31) == 0) red[threadIdx.x >> 5] = s;
    __syncthreads();
    if (threadIdx.x == 0) {
        float v = 0.f;
        for (int i = 0; i < 8; i++) v += red[i];
        g_invn[row] = 1.0f / fmaxf(sqrtf(v), 1e-12f);
    }
}

// ==================== K1: fp16 pre-swizzled tiles ====================
__global__ __launch_bounds__(256) void prep_kernel(const float* __restrict__ hs) {
    size_t i4 = (size_t)blockIdx.x * 256 + threadIdx.x;
    int r  = (int)(i4 / (HDIM / 4));
    int k4 = (int)(i4 % (HDIM / 4)) * 4;
    float4 v = *(const float4*)(hs + (size_t)r * HDIM + k4);
    float vv[4] = {v.x, v.y, v.z, v.w};
    int kc = k4 >> 6;
    int rb = r >> 7, rr = r & 127;
    size_t base = ((size_t)(kc * NRB + rb)) * TILE_ELEMS;
    #pragma unroll
    for (int j = 0; j < 4; j++) {
        int c = (k4 + j) & 63;
        uint32_t off = (uint32_t)(rr * 128 + c * 2);
        uint32_t sw  = (off ^ (((uint32_t)(rr & 7)) << 4)) >> 1;
        g_hi[base + sw] = __float2half(vv[j]);
    }
}

// ==================== K2: sim ~= H H^T via fp16 mma.sync, symmetric ====================
__global__ __launch_bounds__(256, 2) void simgemm_mma(const int* __restrict__ mask) {
    const int bj = blockIdx.x, bi = blockIdx.y;
    if (bi > bj) return;
    extern __shared__ __align__(128) char smem[];
    const uint32_t sbase = smem_u32(smem);
    const int tid = threadIdx.x;
    const int lane = tid & 31, wid = tid >> 5;
    const int wm = wid & 1, wn = wid >> 1;

    float acc[4][4][4];
    #pragma unroll
    for (int a = 0; a < 4; a++)
        #pragma unroll
        for (int b = 0; b < 4; b++)
            #pragma unroll
            for (int c = 0; c < 4; c++) acc[a][b][c] = 0.f;

    const __half* baseA = g_hi + (size_t)bi * TILE_ELEMS;
    const __half* baseB = g_hi + (size_t)bj * TILE_ELEMS;
    const size_t kc_stride = (size_t)NRB * TILE_ELEMS;

    const int rbase = (lane & 7) + ((lane >> 3) & 1) * 8;
    const int csel  = lane >> 4;

    auto issue = [&](int kc, int s) {
        uint32_t sb = sbase + s * STAGE_BYTES;
        const char* sa  = (const char*)(baseA + (size_t)kc * kc_stride);
        const char* sbp = (const char*)(baseB + (size_t)kc * kc_stride);
        #pragma unroll
        for (int i = 0; i < 4; i++) {
            uint32_t o = (uint32_t)(tid * 16 + i * 4096);
            CP16(sb + o, sa + o);
            CP16(sb + TILE_BYTES + o, sbp + o);
        }
        CPCOMMIT();
    };

    issue(0, 0);
    issue(1, 1);

    for (int kc = 0; kc < NKC; kc++) {
        CPWAIT1();
        __syncthreads();
        if (kc + 2 < NKC) issue(kc + 2, (kc + 2) % STAGES);

        uint32_t sb = sbase + (kc % STAGES) * STAGE_BYTES;
        #pragma unroll
        for (int k16 = 0; k16 < 4; k16++) {
            uint32_t ah[4][4], bh[4][2];
            #pragma unroll
            for (int mt = 0; mt < 4; mt++) {
                int row = wm * 64 + mt * 16 + rbase;
                uint32_t off = (uint32_t)(row * 128 + (((k16 * 2 + csel) ^ (row & 7)) * 16));
                LDSM4(ah[mt][0], ah[mt][1], ah[mt][2], ah[mt][3], sb + off);
            }
            #pragma unroll
            for (int p = 0; p < 2; p++) {
                int row = wn * 32 + p * 16 + rbase;
                uint32_t off = (uint32_t)(row * 128 + (((k16 * 2 + csel) ^ (row & 7)) * 16));
                uint32_t r0, r1, r2, r3;
                LDSM4(r0, r1, r2, r3, sb + TILE_BYTES + off);
                bh[2*p][0] = r0; bh[2*p][1] = r2; bh[2*p+1][0] = r1; bh[2*p+1][1] = r3;
            }
            #pragma unroll
            for (int mt = 0; mt < 4; mt++)
                #pragma unroll
                for (int nt = 0; nt < 4; nt++)
                    MMA16816(acc[mt][nt], ah[mt], bh[nt]);
        }
    }
    CPWAIT0();

    const int i0 = bi * 128 + wm * 64;
    const int j0 = bj * 128 + wn * 32;
    const int grp = lane >> 2, qd = lane & 3;
    #pragma unroll
    for (int mt = 0; mt < 4; mt++) {
        #pragma unroll
        for (int half = 0; half < 2; half++) {
            int row = i0 + mt * 16 + grp + half * 8;
            float sa = g_invn[row];
            int mr = mask[row];
            #pragma unroll
            for (int nt = 0; nt < 4; nt++) {
                int col = j0 + nt * 8 + qd * 2;
                float v0 = acc[mt][nt][half * 2 + 0] * sa * g_invn[col];
                float v1 = acc[mt][nt][half * 2 + 1] * sa * g_invn[col + 1];
                float2 o;
                o.x = (row == col     || mask[col]     == 0) ? NEGINF : v0;
                o.y = (row == col + 1 || mask[col + 1] == 0) ? NEGINF : v1;
                *(float2*)(g_sim + (size_t)row * BDIM + col) = o;
                if (bi != bj) {
                    g_sim[(size_t)col * BDIM + row]       = mr ? v0 : NEGINF;
                    g_sim[(size_t)(col + 1) * BDIM + row] = mr ? v1 : NEGINF;
                }
            }
        }
    }
}

// ==================== K3: per-row top-32, contention-free radix select ====================
__device__ __forceinline__ uint32_t f2key(float f) {
    uint32_t b = __float_as_uint(f);
    return (b & 0x80000000u) ? ~b : (b | 0x80000000u);
}
__device__ __forceinline__ float key2f(uint32_t k) {
    return __uint_as_float((k & 0x80000000u) ? (k & 0x7FFFFFFFu) : ~k);
}

__global__ __launch_bounds__(256) void topk_kernel(const float* __restrict__ hs) {
    __shared__ int whist[8][256];            // 8 KB, per-warp private level-0 hist
    __shared__ int hist[256];                // shared level hist
    __shared__ int sbin0, srem0, sbin1, srem1, scnt, sfin;
    __shared__ uint32_t lkey[LCAP];          // 12 KB compact candidate keys
    __shared__ uint16_t lidx[LCAP];          // 6 KB  compact candidate indices
    __shared__ uint32_t fkey[FCAP];
    __shared__ int      fidx[FCAP];
    __shared__ float svals[FCAP];
    __shared__ int   sidxs[FCAP];
    __shared__ float exv[CAND];
    const int row = blockIdx.x;
    const int tid = threadIdx.x, wid = tid >> 5, lid = tid & 31;
    const float* sp = g_sim + (size_t)row * BDIM;

    // ---- pass A: stream row, per-warp private level-0 histograms ----
    {
        int* wh = &whist[0][0];
        for (int i = tid; i < 8 * 256; i += 256) wh[i] = 0;
    }
    __syncthreads();
    for (int c0 = tid * 4; c0 < BDIM; c0 += 1024) {
        float4 v = *(const float4*)(sp + c0);
        const float* vp = &v.x;
        #pragma unroll
        for (int j = 0; j < 4; j++) {
            uint32_t bin = f2key(vp[j]) >> 24;
            uint32_t mg = __match_any_sync(0xffffffffu, bin);
            if (lid == __ffs(mg) - 1) whist[wid][bin] += __popc(mg);
        }
    }
    __syncthreads();
    {
        int t = 0;
        #pragma unroll
        for (int w = 0; w < 8; w++) t += whist[w][tid];
        hist[tid] = t;
    }
    __syncthreads();
    // select level-0 bin: smallest set of top bins with cum >= CAND
    if (tid < 32) {
        int b0 = 248 - 8 * tid;
        int h[8], part = 0;
        #pragma unroll
        for (int q = 0; q < 8; q++) { h[q] = hist[b0 + q]; part += h[q]; }
        int inc = part;
        #pragma unroll
        for (int o = 1; o < 32; o <<= 1) {
            int t = __shfl_up_sync(0xffffffffu, inc, o);
            if (tid >= o) inc += t;
        }
        int pre = inc - part;
        if (pre < CAND && CAND <= inc) {
            int c = pre;
            #pragma unroll
            for (int q = 7; q >= 0; q--) {
                int nb = c + h[q];
                if (nb >= CAND) { sbin0 = b0 + q; srem0 = CAND - c; break; }
                c = nb;
            }
        }
    }
    __syncthreads();
    const uint32_t bound0 = (uint32_t)sbin0 << 24;
    const int rem0 = srem0;

    // ---- pass B: gather all elements with key >= bound0 (warp-aggregated) ----
    if (tid == 0) scnt = 0;
    __syncthreads();
    for (int c0 = tid * 4; c0 < BDIM; c0 += 1024) {
        float4 v = *(const float4*)(sp + c0);
        const float* vp = &v.x;
        #pragma unroll
        for (int j = 0; j < 4; j++) {
            uint32_t k = f2key(vp[j]);
            bool pred = (k >= bound0);
            uint32_t bal = __ballot_sync(0xffffffffu, pred);
            if (bal) {
                int leader = __ffs(bal) - 1;
                int b0v = 0;
                if (lid == leader) b0v = atomicAdd(&scnt, __popc(bal));
                b0v = __shfl_sync(0xffffffffu, b0v, leader);
                if (pred) {
                    int p = b0v + __popc(bal & ((1u << lid) - 1u));
                    if (p < LCAP) { lkey[p] = k; lidx[p] = (uint16_t)(c0 + j); }
                }
            }
        }
    }
    __syncthreads();
    const int n = (scnt < LCAP) ? scnt : LCAP;

    // ---- level 1 on compact list (in-bin elements only) ----
    hist[tid] = 0;
    __syncthreads();
    for (int i = tid; i < n; i += 256) {
        uint32_t k = lkey[i];
        if ((k >> 24) == (uint32_t)sbin0) atomicAdd(&hist[(k >> 16) & 255u], 1);
    }
    __syncthreads();
    if (tid < 32) {
        int b0 = 248 - 8 * tid;
        int h[8], part = 0;
        #pragma unroll
        for (int q = 0; q < 8; q++) { h[q] = hist[b0 + q]; part += h[q]; }
        int inc = part;
        #pragma unroll
        for (int o = 1; o < 32; o <<= 1) {
            int t = __shfl_up_sync(0xffffffffu, inc, o);
            if (tid >= o) inc += t;
        }
        int pre = inc - part;
        if (pre < rem0 && rem0 <= inc) {
            int c = pre;
            #pragma unroll
            for (int q = 7; q >= 0; q--) {
                int nb = c + h[q];
                if (nb >= rem0) { sbin1 = b0 + q; srem1 = rem0 - c; break; }
                c = nb;
            }
        }
    }
    __syncthreads();
    const uint32_t prefix16 = ((uint32_t)sbin0 << 8) | (uint32_t)sbin1;

    // ---- final gather: elements with (key>>16) >= prefix16 ----
    if (tid == 0) sfin = 0;
    __syncthreads();
    for (int i = tid; i < n; i += 256) {
        uint32_t k = lkey[i];
        if ((k >> 16) >= prefix16) {
            int p = atomicAdd(&sfin, 1);
            if (p < FCAP) { fkey[p] = k; fidx[p] = (int)lidx[i]; }
        }
    }
    __syncthreads();
    const int m = (sfin < FCAP) ? sfin : FCAP;

    // ---- rank sort descending (stable by index) ----
    if (tid < m) {
        uint32_t k = fkey[tid]; int ix = fidx[tid];
        int r = 0;
        for (int j = 0; j < m; j++) {
            uint32_t kj = fkey[j];
            if (kj > k || (kj == k && fidx[j] < ix)) r++;
        }
        if (r < FCAP) { svals[r] = key2f(k); sidxs[r] = ix; }
    }
    __syncthreads();

    // ---- exact-fp32 fixup when rank32/33 gap is within fp16 error reach ----
    bool need = (svals[TOPK - 1] - svals[TOPK]) < 1e-4f;
    if (need) {
        const float* hrow = hs + (size_t)row * HDIM;
        float inr = g_invn[row];
        for (int c = wid; c < CAND; c += 8) {
            int idx = sidxs[c];
            const float* hc = hs + (size_t)idx * HDIM;
            float d = 0.f;
            for (int q = lid; q < HDIM; q += 32) d = fmaf(hrow[q], hc[q], d);
            #pragma unroll
            for (int o = 16; o; o >>= 1) d += __shfl_down_sync(0xffffffffu, d, o);
            if (lid == 0) exv[c] = d * inr * g_invn[idx];
        }
        __syncthreads();
        if (tid == 0) {
            float fv[TOPK]; int fi[TOPK];
            bool used[CAND];
            for (int c = 0; c < CAND; c++) used[c] = false;
            for (int it = 0; it < TOPK; it++) {
                float bv = NEGINF; int bc = -1;
                for (int c = 0; c < CAND; c++)
                    if (!used[c] && (bc < 0 || exv[c] > bv)) { bv = exv[c]; bc = c; }
                used[bc] = true;
                fv[it] = bv; fi[it] = sidxs[bc];
            }
            for (int it = 0; it < TOPK; it++) { svals[it] = fv[it]; sidxs[it] = fi[it]; }
        }
        __syncthreads();
    }

    // ---- softmax over top-32 ----
    if (tid < TOPK) {
        float mm = svals[0];
        float v = svals[tid];
        float e = (isfinite(v) && isfinite(mm)) ? __expf(v - mm) : 0.f;
        float s = e;
        for (int o = 16; o; o >>= 1) s += __shfl_down_sync(0xffffffffu, s, o);
        s = __shfl_sync(0xffffffffu, s, 0);
        float w = (s > 0.f) ? e / s : 0.f;
        g_topw[row * TOPK + tid] = w;
        g_topidx[row * TOPK + tid] = sidxs[tid];
    }
}

// ==================== K4: sparse cross + gate + residual ====================
__global__ __launch_bounds__(256) void cross_gate_kernel(const float* __restrict__ hs,
                                                         const float* __restrict__ gw,
                                                         const float* __restrict__ gb,
                                                         float* __restrict__ out) {
    const int row = blockIdx.x;
    const int tid = threadIdx.x;
    __shared__ float sw[TOPK];
    __shared__ int   si[TOPK];
    __shared__ float red[8];
    __shared__ float gsh;
    if (tid < TOPK) { sw[tid] = g_topw[row * TOPK + tid]; si[tid] = g_topidx[row * TOPK + tid]; }
    __syncthreads();

    float cr[HDIM / 256];
    float p = 0.f;
    #pragma unroll
    for (int u = 0; u < HDIM / 256; u++) {
        int c = tid + u * 256;
        float acc = 0.f;
        #pragma unroll
        for (int k = 0; k < TOPK; k++)
            acc = fmaf(sw[k], hs[(size_t)si[k] * HDIM + c], acc);
        cr[u] = acc;
        float h = hs[(size_t)row * HDIM + c];
        p = fmaf(gw[c], h, p);
        p = fmaf(gw[HDIM + c], acc, p);
    }
    for (int o = 16; o; o >>= 1) p += __shfl_down_sync(0xffffffffu, p, o);
    if ((tid & 31) == 0) red[tid >> 5] = p;
    __syncthreads();
    if (tid == 0) {
        float v = 0.f;
        for (int i = 0; i < 8; i++) v += red[i];
        gsh = 1.f / (1.f + __expf(-(v + gb[0])));
    }
    __syncthreads();
    float g = gsh;
    #pragma unroll
    for (int u = 0; u < HDIM / 256; u++) {
        int c = tid + u * 256;
        float h = hs[(size_t)row * HDIM + c];
        out[(size_t)row * HDIM + c] = h + g * cr[u];
    }
}

// ==================== launch ====================
extern "C" void kernel_launch(void* const* d_in, const int* in_sizes, int n_in,
                              void* d_out, int out_size) {
    const float* hs  = (const float*)d_in[0];
    const int*   msk = (const int*)d_in[1];
    const float* gw  = (const float*)d_in[2];
    const float* gb  = (const float*)d_in[3];
    float* out       = (float*)d_out;

    static int smem_set = 0;
    if (!smem_set) {
        cudaFuncSetAttribute(simgemm_mma, cudaFuncAttributeMaxDynamicSharedMemorySize, SMEM_TOTAL);
        smem_set = 1;
    }

    norms_kernel<<<BDIM, 256>>>(hs);
    prep_kernel<<<(BDIM * (HDIM / 4)) / 256, 256>>>(hs);
    dim3 grid(NRB, NRB);
    simgemm_mma<<<grid, 256, SMEM_TOTAL>>>(msk);
    topk_kernel<<<BDIM, 256>>>(hs);
    cross_gate_kernel<<<BDIM, 256>>>(hs, gw, gb, out);
}